// round 9
// baseline (speedup 1.0000x reference)
#include <cuda_runtime.h>
#include <cstdint>

#define N_NODES 100000
#define FEAT    64
#define NF      (N_NODES * FEAT)
#define E_MAX   1700000
#define GRID    444            // 3 blocks/SM on 148 SMs (co-resident, barrier-safe)
#define TPB     512
#define CHUNK   226            // ceil(N_NODES / GRID); 444*226 = 100344
#define NBAR    8

// Scratch: device globals (no allocations allowed). Zero-initialized.
__device__ __align__(16) float g_u[NF];
__device__ __align__(16) float g_u2[NF];
__device__ int   g_cnt[N_NODES];
__device__ int   g_off[N_NODES + 1];
__device__ int   g_cur[N_NODES];
__device__ int   g_adj[E_MAX];
__device__ int   g_blk[GRID];
__device__ float g_dinv[N_NODES];    // (deg)^{-1/2}, deg includes self-loop
__device__ float g_dinv2[N_NODES];   // (deg)^{-1}
__device__ int   g_is64;             // 1 if edge_index is int64, 0 if int32
// Grid barrier state. Slot k's flag is reset at release of slot k+1 (circular),
// so all state returns to a reusable configuration every launch (replay-safe).
__device__ unsigned      g_bar_cnt[NBAR];
__device__ volatile int  g_bar_flag[NBAR];

// ---------------------------------------------------------------------------
__device__ __forceinline__ void grid_barrier(int slot) {
    __syncthreads();
    if (threadIdx.x == 0) {
        __threadfence();
        unsigned old = atomicAdd(&g_bar_cnt[slot], 1u);
        if (old == GRID - 1) {
            g_bar_cnt[slot] = 0;                          // self-clean counter
            g_bar_flag[(slot + NBAR - 1) % NBAR] = 0;     // reset previous slot
            __threadfence();
            g_bar_flag[slot] = 1;                         // release
        } else {
            while (g_bar_flag[slot] == 0) { __nanosleep(64); }
            __threadfence();
        }
    }
    __syncthreads();
}

__device__ __forceinline__ int edge_idx(const void* ei, int E, int half, int e) {
    if (g_is64) return (int)((const long long*)ei)[(size_t)half * E + e];
    return ((const int*)ei)[(size_t)half * E + e];
}

// ---------------------------------------------------------------------------
// Gather hop: halfwarp (16 threads) per node, one float4 column-group each.
// PASS 0: g_u -> g_u2 (dinv2); PASS 1: g_u2 -> g_u (dinv2);
// PASS 2: g_u -> out (dinv, +bias).
template <int PASS>
__device__ void hop_phase(float* __restrict__ outp, const float* __restrict__ b) {
    const float4* uin = reinterpret_cast<const float4*>(PASS == 1 ? g_u2 : g_u);
    float4* uout = (PASS == 0) ? reinterpret_cast<float4*>(g_u2)
                 : (PASS == 1) ? reinterpret_cast<float4*>(g_u)
                               : reinterpret_cast<float4*>(outp);
    int lane = threadIdx.x & 15;
    int hw   = threadIdx.x >> 4;        // 0..31 halfwarps per block

    for (int base = blockIdx.x * 32; base < N_NODES; base += GRID * 32) {
        int node = base + hw;
        if (node >= N_NODES) continue;

        int d   = g_off[node];
        int end = g_off[node + 1];

        float4 s0 = uin[(size_t)node * 16 + lane];   // self-loop term
        float4 s1 = make_float4(0.f, 0.f, 0.f, 0.f);

        for (; d + 3 < end; d += 4) {
            int j0 = __ldg(&g_adj[d + 0]);
            int j1 = __ldg(&g_adj[d + 1]);
            int j2 = __ldg(&g_adj[d + 2]);
            int j3 = __ldg(&g_adj[d + 3]);
            float4 a0 = __ldg(&uin[(size_t)j0 * 16 + lane]);
            float4 a1 = __ldg(&uin[(size_t)j1 * 16 + lane]);
            float4 a2 = __ldg(&uin[(size_t)j2 * 16 + lane]);
            float4 a3 = __ldg(&uin[(size_t)j3 * 16 + lane]);
            s0.x += a0.x + a1.x;  s0.y += a0.y + a1.y;
            s0.z += a0.z + a1.z;  s0.w += a0.w + a1.w;
            s1.x += a2.x + a3.x;  s1.y += a2.y + a3.y;
            s1.z += a2.z + a3.z;  s1.w += a2.w + a3.w;
        }
        for (; d < end; d++) {
            int j0 = __ldg(&g_adj[d]);
            float4 a0 = __ldg(&uin[(size_t)j0 * 16 + lane]);
            s0.x += a0.x; s0.y += a0.y; s0.z += a0.z; s0.w += a0.w;
        }
        s0.x += s1.x; s0.y += s1.y; s0.z += s1.z; s0.w += s1.w;

        float4 o;
        if (PASS == 2) {
            float sc = g_dinv[node];
            int cb = lane << 2;
            o.x = sc * s0.x + __ldg(&b[cb + 0]);
            o.y = sc * s0.y + __ldg(&b[cb + 1]);
            o.z = sc * s0.z + __ldg(&b[cb + 2]);
            o.w = sc * s0.w + __ldg(&b[cb + 3]);
        } else {
            float sc = g_dinv2[node];
            o.x = sc * s0.x; o.y = sc * s0.y; o.z = sc * s0.z; o.w = sc * s0.w;
        }
        uout[(size_t)node * 16 + lane] = o;
    }
}

// ---------------------------------------------------------------------------
__global__ void __launch_bounds__(TPB, 3)
sgc_mono(const float* __restrict__ x, const void* __restrict__ ei, int E,
         const float* __restrict__ W, const float* __restrict__ b,
         float* __restrict__ out) {
    __shared__ __align__(16) char s_mem[34944];   // gemm: Ws 32768 + xs 2048
    float* Ws = reinterpret_cast<float*>(s_mem);              // [128*64]
    float* xs = reinterpret_cast<float*>(s_mem + 32768);      // [4*128]
    int*   bs = reinterpret_cast<int*>(s_mem);                // scan scratch

    const int tid = threadIdx.x;
    const int bid = blockIdx.x;
    const int gthread = bid * TPB + tid;
    const int gstride = GRID * TPB;

    // ---- Phase 0: zero histogram + dtype detect ---------------------------
    for (int i = gthread; i < N_NODES; i += gstride) g_cnt[i] = 0;
    if (bid == 0) {
        __shared__ int any;
        if (tid == 0) any = 0;
        __syncthreads();
        const int* ei32 = (const int*)ei;
        for (int i = tid; i < 1024; i += TPB)
            if (ei32[2 * i + 1] != 0) any = 1;   // benign race
        __syncthreads();
        if (tid == 0) g_is64 = (any == 0) ? 1 : 0;
    }
    grid_barrier(0);

    // ---- Phase 1: degree histogram ----------------------------------------
    for (int e = gthread; e < E; e += gstride) {
        unsigned t = (unsigned)edge_idx(ei, E, 1, e);
        if (t < N_NODES) atomicAdd(&g_cnt[t], 1);
    }
    grid_barrier(1);

    // ---- Phase 2: per-block chunk sums ------------------------------------
    {
        int beg = bid * CHUNK;
        int len = N_NODES - beg; if (len > CHUNK) len = CHUNK; if (len < 0) len = 0;
        int v = (tid < len) ? g_cnt[beg + tid] : 0;
        bs[tid] = v;
        __syncthreads();
        for (int off = TPB / 2; off > 0; off >>= 1) {
            if (tid < off) bs[tid] += bs[tid + off];
            __syncthreads();
        }
        if (tid == 0) g_blk[bid] = bs[0];
    }
    grid_barrier(2);

    // ---- Phase 3: block 0 scans the 444 block sums ------------------------
    if (bid == 0) {
        int v = (tid < GRID) ? g_blk[tid] : 0;
        bs[tid] = v;
        __syncthreads();
        for (int off = 1; off < TPB; off <<= 1) {    // Hillis-Steele inclusive
            int p = (tid >= off) ? bs[tid - off] : 0;
            __syncthreads();
            bs[tid] += p;
            __syncthreads();
        }
        if (tid < GRID) g_blk[tid] = bs[tid] - v;    // exclusive
        if (tid == 0) g_off[N_NODES] = bs[TPB - 1];
    }
    grid_barrier(3);

    // ---- Phase 4: per-chunk exclusive scan + dinv/dinv2 --------------------
    {
        int beg = bid * CHUNK;
        int len = N_NODES - beg; if (len > CHUNK) len = CHUNK; if (len < 0) len = 0;
        int c = (tid < len) ? g_cnt[beg + tid] : 0;
        bs[tid] = c;
        __syncthreads();
        for (int off = 1; off < TPB; off <<= 1) {
            int p = (tid >= off) ? bs[tid - off] : 0;
            __syncthreads();
            bs[tid] += p;
            __syncthreads();
        }
        if (tid < len) {
            int excl = g_blk[bid] + bs[tid] - c;
            int i = beg + tid;
            g_off[i] = excl;
            g_cur[i] = excl;
            float deg = (float)c + 1.0f;
            g_dinv[i]  = rsqrtf(deg);
            g_dinv2[i] = 1.0f / deg;
        }
    }
    grid_barrier(4);

    // ---- Phase 5: scatter (CSR fill) then GEMM (independent, no barrier) --
    for (int e = gthread; e < E; e += gstride) {
        unsigned t = (unsigned)edge_idx(ei, E, 1, e);
        unsigned s = (unsigned)edge_idx(ei, E, 0, e);
        if (t >= N_NODES || s >= N_NODES) continue;
        int pos = atomicAdd(&g_cur[t], 1);
        if (pos < E_MAX) g_adj[pos] = (int)s;
    }
    // GEMM: u0[i,:] = dinv[i] * (x[i,:] @ W^T)
    {
        __syncthreads();   // bs scratch -> Ws reuse
        for (int i = tid; i < 2048; i += TPB) {
            float4 w4 = __ldg(&reinterpret_cast<const float4*>(W)[i]);
            int c = i >> 5;
            int k = (i & 31) << 2;
            Ws[(k + 0) * 64 + c] = w4.x;
            Ws[(k + 1) * 64 + c] = w4.y;
            Ws[(k + 2) * 64 + c] = w4.z;
            Ws[(k + 3) * 64 + c] = w4.w;
        }
        __syncthreads();
        int c = tid & 63;
        int r = tid >> 6;   // 0..7, two thread-groups per row (rows 0..3 twice)
        int rr4 = r & 3;    // row within 4-row tile
        int half = r >> 2;  // 0: cols via c, 1: same (dup) -- instead split K
        // 8 groups of 64 threads over 4 rows: groups 0-3 rows, groups 4-7 same
        // rows -> split the K range instead to keep all threads busy.
        for (int rb = bid * 4; rb < N_NODES; rb += GRID * 4) {
            if (tid < 128) {
                int rr = tid >> 5;          // row 0..3
                int k4 = tid & 31;
                int rowi = rb + rr;
                float4 v = (rowi < N_NODES)
                    ? __ldg(&reinterpret_cast<const float4*>(x)[(size_t)rowi * 32 + k4])
                    : make_float4(0.f, 0.f, 0.f, 0.f);
                int k = k4 << 2;
                xs[rr * 128 + k + 0] = v.x;
                xs[rr * 128 + k + 1] = v.y;
                xs[rr * 128 + k + 2] = v.z;
                xs[rr * 128 + k + 3] = v.w;
            }
            __syncthreads();
            int rowi = rb + rr4;
            if (rowi < N_NODES) {
                // half 0 sums k=0..63, half 1 sums k=64..127
                float s = 0.0f;
                int k0 = half << 6;
                #pragma unroll
                for (int k = 0; k < 64; k++)
                    s = fmaf(xs[rr4 * 128 + k0 + k], Ws[(k0 + k) * 64 + c], s);
                // combine the two halves via shared xs slot reuse-free path:
                // use atomic-free split: half 0 writes, half 1 adds after sync
                if (half == 0) {
                    g_u[(size_t)rowi * 64 + c] = s;
                }
                __syncthreads();
                if (half == 1) {
                    float t0 = g_u[(size_t)rowi * 64 + c];
                    g_u[(size_t)rowi * 64 + c] = g_dinv[rowi] * (t0 + s);
                }
            } else {
                __syncthreads();
            }
            __syncthreads();
        }
    }
    grid_barrier(5);

    // ---- Phases 6-8: three gather hops -------------------------------------
    hop_phase<0>(nullptr, b);
    grid_barrier(6);
    hop_phase<1>(nullptr, b);
    grid_barrier(7);
    hop_phase<2>(out, b);
}

// ---------------------------------------------------------------------------
extern "C" void kernel_launch(void* const* d_in, const int* in_sizes, int n_in,
                              void* d_out, int out_size) {
    const float* x  = (const float*)d_in[0];   // [100000,128]
    const void*  ei = d_in[1];                 // [2, E] int32 or int64
    const float* W  = (const float*)d_in[2];   // [64,128]
    const float* b  = (const float*)d_in[3];   // [64]
    float* out = (float*)d_out;

    const int E = in_sizes[1] / 2;             // 1,600,000

    sgc_mono<<<GRID, TPB>>>(x, ei, E, W, b, out);
}

// round 10
// speedup vs baseline: 1.1368x; 1.1368x over previous
#include <cuda_runtime.h>
#include <cuda_fp16.h>
#include <cstdint>

#define N_NODES 100000
#define FEAT    64
#define NF      (N_NODES * FEAT)
#define E_MAX   1700000
#define GRID    444            // 3 blocks/SM on 148 SMs (co-resident, barrier-safe)
#define TPB     512
#define CHUNK   226            // ceil(N_NODES / GRID)
#define NBAR    8

// Scratch: device globals (no allocations allowed). Zero-initialized.
__device__ __align__(16) __half2 g_uh[NF / 2];   // fp16 feature buffers
__device__ __align__(16) __half2 g_uh2[NF / 2];
__device__ int   g_cnt[N_NODES];
__device__ int   g_off[N_NODES + 1];
__device__ int   g_cur[N_NODES];
__device__ int   g_adj[E_MAX];
__device__ int   g_blk[GRID];
__device__ float g_dinv[N_NODES];    // (deg)^{-1/2}, deg includes self-loop
__device__ float g_dinv2[N_NODES];   // (deg)^{-1}
__device__ int   g_is64;             // 1 if edge_index is int64, 0 if int32
// Grid barrier state; slot k's flag resets at release of slot k+1 (circular),
// so state returns to a reusable configuration every launch (replay-safe).
__device__ unsigned      g_bar_cnt[NBAR];
__device__ volatile int  g_bar_flag[NBAR];

// ---------------------------------------------------------------------------
__device__ __forceinline__ void grid_barrier(int slot) {
    __syncthreads();
    if (threadIdx.x == 0) {
        __threadfence();
        unsigned old = atomicAdd(&g_bar_cnt[slot], 1u);
        if (old == GRID - 1) {
            g_bar_cnt[slot] = 0;
            g_bar_flag[(slot + NBAR - 1) % NBAR] = 0;
            __threadfence();
            g_bar_flag[slot] = 1;
        } else {
            while (g_bar_flag[slot] == 0) { __nanosleep(64); }
            __threadfence();
        }
    }
    __syncthreads();
}

__device__ __forceinline__ int edge_idx(const void* ei, int E, int half, int e) {
    if (g_is64) return (int)((const long long*)ei)[(size_t)half * E + e];
    return ((const int*)ei)[(size_t)half * E + e];
}

// ---------------------------------------------------------------------------
// Gather hop: ONE WARP per node; lane owns feature pair (2*lane, 2*lane+1).
// One edge gather = 32 lanes x 4B = 128B = single cache line.
// PASS 0: g_uh -> g_uh2 (dinv2); PASS 1: g_uh2 -> g_uh (dinv2);
// PASS 2: g_uh -> out fp32 (dinv, +bias).
template <int PASS>
__device__ void hop_phase(float* __restrict__ outp, const float* __restrict__ b) {
    const __half2* uin = (PASS == 1) ? g_uh2 : g_uh;
    __half2* uout = (PASS == 0) ? g_uh2 : g_uh;
    int lane = threadIdx.x & 31;
    int w    = threadIdx.x >> 5;         // 0..15 warps per block

    for (int node = blockIdx.x * 16 + w; node < N_NODES; node += GRID * 16) {
        int d   = g_off[node];
        int end = g_off[node + 1];

        float2 s0 = __half22float2(uin[(size_t)node * 32 + lane]);  // self
        float2 s1 = make_float2(0.f, 0.f);

        for (; d + 3 < end; d += 4) {
            int j0 = __ldg(&g_adj[d + 0]);
            int j1 = __ldg(&g_adj[d + 1]);
            int j2 = __ldg(&g_adj[d + 2]);
            int j3 = __ldg(&g_adj[d + 3]);
            float2 a0 = __half22float2(__ldg(&uin[(size_t)j0 * 32 + lane]));
            float2 a1 = __half22float2(__ldg(&uin[(size_t)j1 * 32 + lane]));
            float2 a2 = __half22float2(__ldg(&uin[(size_t)j2 * 32 + lane]));
            float2 a3 = __half22float2(__ldg(&uin[(size_t)j3 * 32 + lane]));
            s0.x += a0.x + a1.x;  s0.y += a0.y + a1.y;
            s1.x += a2.x + a3.x;  s1.y += a2.y + a3.y;
        }
        for (; d < end; d++) {
            int j0 = __ldg(&g_adj[d]);
            float2 a0 = __half22float2(__ldg(&uin[(size_t)j0 * 32 + lane]));
            s0.x += a0.x; s0.y += a0.y;
        }
        s0.x += s1.x; s0.y += s1.y;

        if (PASS == 2) {
            float sc = g_dinv[node];
            float2 o;
            o.x = sc * s0.x + __ldg(&b[2 * lane + 0]);
            o.y = sc * s0.y + __ldg(&b[2 * lane + 1]);
            reinterpret_cast<float2*>(outp)[(size_t)node * 32 + lane] = o;
        } else {
            float sc = g_dinv2[node];
            uout[(size_t)node * 32 + lane] = __floats2half2_rn(sc * s0.x, sc * s0.y);
        }
    }
}

// ---------------------------------------------------------------------------
__global__ void __launch_bounds__(TPB, 3)
sgc_mono(const float* __restrict__ x, const void* __restrict__ ei, int E,
         const float* __restrict__ W, const float* __restrict__ b,
         float* __restrict__ out) {
    __shared__ __align__(16) char s_mem[40960];   // gemm: Ws 32768 + xs 8192
    float* Ws = reinterpret_cast<float*>(s_mem);              // [128*64]
    float* xs = reinterpret_cast<float*>(s_mem + 32768);      // [16*128]
    int*   bs = reinterpret_cast<int*>(s_mem);                // scan scratch

    const int tid = threadIdx.x;
    const int bid = blockIdx.x;
    const int gthread = bid * TPB + tid;
    const int gstride = GRID * TPB;

    // ---- Phase 0: zero histogram + dtype detect ---------------------------
    for (int i = gthread; i < N_NODES; i += gstride) g_cnt[i] = 0;
    if (bid == 0) {
        __shared__ int any;
        if (tid == 0) any = 0;
        __syncthreads();
        const int* ei32 = (const int*)ei;
        for (int i = tid; i < 1024; i += TPB)
            if (ei32[2 * i + 1] != 0) any = 1;   // benign race
        __syncthreads();
        if (tid == 0) g_is64 = (any == 0) ? 1 : 0;
    }
    grid_barrier(0);

    // ---- Phase 1: degree histogram ----------------------------------------
    for (int e = gthread; e < E; e += gstride) {
        unsigned t = (unsigned)edge_idx(ei, E, 1, e);
        if (t < N_NODES) atomicAdd(&g_cnt[t], 1);
    }
    grid_barrier(1);

    // ---- Phase 2: per-block chunk sums ------------------------------------
    {
        int beg = bid * CHUNK;
        int len = N_NODES - beg; if (len > CHUNK) len = CHUNK; if (len < 0) len = 0;
        int v = (tid < len) ? g_cnt[beg + tid] : 0;
        bs[tid] = v;
        __syncthreads();
        for (int off = TPB / 2; off > 0; off >>= 1) {
            if (tid < off) bs[tid] += bs[tid + off];
            __syncthreads();
        }
        if (tid == 0) g_blk[bid] = bs[0];
    }
    grid_barrier(2);

    // ---- Phase 3: block 0 scans the 444 block sums ------------------------
    if (bid == 0) {
        int v = (tid < GRID) ? g_blk[tid] : 0;
        bs[tid] = v;
        __syncthreads();
        for (int off = 1; off < TPB; off <<= 1) {    // Hillis-Steele inclusive
            int p = (tid >= off) ? bs[tid - off] : 0;
            __syncthreads();
            bs[tid] += p;
            __syncthreads();
        }
        if (tid < GRID) g_blk[tid] = bs[tid] - v;    // exclusive
        if (tid == 0) g_off[N_NODES] = bs[TPB - 1];
    }
    grid_barrier(3);

    // ---- Phase 4: per-chunk exclusive scan + dinv/dinv2 --------------------
    {
        int beg = bid * CHUNK;
        int len = N_NODES - beg; if (len > CHUNK) len = CHUNK; if (len < 0) len = 0;
        int c = (tid < len) ? g_cnt[beg + tid] : 0;
        bs[tid] = c;
        __syncthreads();
        for (int off = 1; off < TPB; off <<= 1) {
            int p = (tid >= off) ? bs[tid - off] : 0;
            __syncthreads();
            bs[tid] += p;
            __syncthreads();
        }
        if (tid < len) {
            int excl = g_blk[bid] + bs[tid] - c;
            int i = beg + tid;
            g_off[i] = excl;
            g_cur[i] = excl;
            float deg = (float)c + 1.0f;
            g_dinv[i]  = rsqrtf(deg);
            g_dinv2[i] = 1.0f / deg;
        }
    }
    grid_barrier(4);

    // ---- Phase 5: scatter (CSR fill) then GEMM (independent) ---------------
    for (int e = gthread; e < E; e += gstride) {
        unsigned t = (unsigned)edge_idx(ei, E, 1, e);
        unsigned s = (unsigned)edge_idx(ei, E, 0, e);
        if (t >= N_NODES || s >= N_NODES) continue;
        int pos = atomicAdd(&g_cur[t], 1);
        if (pos < E_MAX) g_adj[pos] = (int)s;
    }
    // GEMM: u0[i,:] = dinv[i] * (x[i,:] @ W^T), stored fp16.
    // 512 threads = 16 rows x 32 half2-columns.
    {
        __syncthreads();   // bs scratch -> Ws reuse
        for (int i = tid; i < 2048; i += TPB) {
            float4 w4 = __ldg(&reinterpret_cast<const float4*>(W)[i]);
            int c = i >> 5;
            int k = (i & 31) << 2;
            Ws[(k + 0) * 64 + c] = w4.x;
            Ws[(k + 1) * 64 + c] = w4.y;
            Ws[(k + 2) * 64 + c] = w4.z;
            Ws[(k + 3) * 64 + c] = w4.w;
        }
        __syncthreads();
        int c = tid & 31;     // half2 column pair (2c, 2c+1)
        int r = tid >> 5;     // row 0..15
        const float2* Ws2 = reinterpret_cast<const float2*>(Ws);
        for (int rb = bid * 16; rb < N_NODES; rb += GRID * 16) {
            {   // stage 16 rows of x: 512 float4, one per thread
                int rr = tid >> 5;
                int k4 = tid & 31;
                int rowi = rb + rr;
                float4 v = (rowi < N_NODES)
                    ? __ldg(&reinterpret_cast<const float4*>(x)[(size_t)rowi * 32 + k4])
                    : make_float4(0.f, 0.f, 0.f, 0.f);
                int k = k4 << 2;
                xs[rr * 128 + k + 0] = v.x;
                xs[rr * 128 + k + 1] = v.y;
                xs[rr * 128 + k + 2] = v.z;
                xs[rr * 128 + k + 3] = v.w;
            }
            __syncthreads();
            int rowi = rb + r;
            if (rowi < N_NODES) {
                float s0 = 0.f, s1 = 0.f;
                #pragma unroll
                for (int k = 0; k < 128; k++) {
                    float xv = xs[r * 128 + k];
                    float2 w2 = Ws2[k * 32 + c];
                    s0 = fmaf(xv, w2.x, s0);
                    s1 = fmaf(xv, w2.y, s1);
                }
                float sc = g_dinv[rowi];
                g_uh[(size_t)rowi * 32 + c] = __floats2half2_rn(sc * s0, sc * s1);
            }
            __syncthreads();
        }
    }
    grid_barrier(5);

    // ---- Phases 6-8: three gather hops -------------------------------------
    hop_phase<0>(nullptr, b);
    grid_barrier(6);
    hop_phase<1>(nullptr, b);
    grid_barrier(7);
    hop_phase<2>(out, b);
}

// ---------------------------------------------------------------------------
extern "C" void kernel_launch(void* const* d_in, const int* in_sizes, int n_in,
                              void* d_out, int out_size) {
    const float* x  = (const float*)d_in[0];   // [100000,128]
    const void*  ei = d_in[1];                 // [2, E] int32 or int64
    const float* W  = (const float*)d_in[2];   // [64,128]
    const float* b  = (const float*)d_in[3];   // [64]
    float* out = (float*)d_out;

    const int E = in_sizes[1] / 2;             // 1,600,000

    sgc_mono<<<GRID, TPB>>>(x, ei, E, W, b, out);
}

// round 11
// speedup vs baseline: 1.2566x; 1.1054x over previous
#include <cuda_runtime.h>
#include <cuda_fp16.h>
#include <cstdint>

#define N_NODES 100000
#define FEAT    64
#define NF      (N_NODES * FEAT)
#define E_MAX   1700000
#define GRID    296            // 2 blocks/SM on 148 SMs (co-resident, barrier-safe)
#define TPB     512
#define CHUNK   338            // ceil(N_NODES / GRID)
#define NBAR    8

// Scratch: device globals (no allocations allowed). Zero-initialized.
__device__ __align__(16) __half2 g_uh[NF / 2];   // fp16 feature buffers
__device__ __align__(16) __half2 g_uh2[NF / 2];
__device__ int   g_cnt[N_NODES];
__device__ int   g_off[N_NODES + 1];
__device__ int   g_cur[N_NODES];
__device__ int   g_adj[E_MAX];
__device__ int   g_blk[GRID];
__device__ float g_dinv[N_NODES];    // (deg)^{-1/2}, deg includes self-loop
__device__ float g_dinv2[N_NODES];   // (deg)^{-1}
__device__ int   g_is64;             // 1 if edge_index is int64, 0 if int32
// Grid barrier state; slot k's flag resets at release of slot k+1 (circular),
// so state returns to a reusable configuration every launch (replay-safe).
__device__ unsigned      g_bar_cnt[NBAR];
__device__ volatile int  g_bar_flag[NBAR];

// ---------------------------------------------------------------------------
__device__ __forceinline__ void grid_barrier(int slot) {
    __syncthreads();
    if (threadIdx.x == 0) {
        __threadfence();
        unsigned old = atomicAdd(&g_bar_cnt[slot], 1u);
        if (old == GRID - 1) {
            g_bar_cnt[slot] = 0;
            g_bar_flag[(slot + NBAR - 1) % NBAR] = 0;
            __threadfence();
            g_bar_flag[slot] = 1;
        } else {
            while (g_bar_flag[slot] == 0) { __nanosleep(64); }
            __threadfence();
        }
    }
    __syncthreads();
}

__device__ __forceinline__ int edge_idx(const void* ei, int E, int half, int e) {
    if (g_is64) return (int)((const long long*)ei)[(size_t)half * E + e];
    return ((const int*)ei)[(size_t)half * E + e];
}

// ---------------------------------------------------------------------------
// Gather hop: ONE WARP per node; lane owns feature pair (2*lane, 2*lane+1).
// One edge gather = 32 lanes x 4B = 128B = single cache line.
// PASS 0: g_uh -> g_uh2 (dinv2); PASS 1: g_uh2 -> g_uh (dinv2);
// PASS 2: g_uh -> out fp32 (dinv, +bias).
template <int PASS>
__device__ void hop_phase(float* __restrict__ outp, const float* __restrict__ b) {
    const __half2* uin = (PASS == 1) ? g_uh2 : g_uh;
    __half2* uout = (PASS == 0) ? g_uh2 : g_uh;
    int lane = threadIdx.x & 31;
    int w    = threadIdx.x >> 5;         // 0..15 warps per block

    for (int node = blockIdx.x * 16 + w; node < N_NODES; node += GRID * 16) {
        int d   = g_off[node];
        int end = g_off[node + 1];

        float2 s0 = __half22float2(uin[(size_t)node * 32 + lane]);  // self
        float2 s1 = make_float2(0.f, 0.f);

        for (; d + 3 < end; d += 4) {
            int j0 = __ldg(&g_adj[d + 0]);
            int j1 = __ldg(&g_adj[d + 1]);
            int j2 = __ldg(&g_adj[d + 2]);
            int j3 = __ldg(&g_adj[d + 3]);
            float2 a0 = __half22float2(__ldg(&uin[(size_t)j0 * 32 + lane]));
            float2 a1 = __half22float2(__ldg(&uin[(size_t)j1 * 32 + lane]));
            float2 a2 = __half22float2(__ldg(&uin[(size_t)j2 * 32 + lane]));
            float2 a3 = __half22float2(__ldg(&uin[(size_t)j3 * 32 + lane]));
            s0.x += a0.x + a1.x;  s0.y += a0.y + a1.y;
            s1.x += a2.x + a3.x;  s1.y += a2.y + a3.y;
        }
        for (; d < end; d++) {
            int j0 = __ldg(&g_adj[d]);
            float2 a0 = __half22float2(__ldg(&uin[(size_t)j0 * 32 + lane]));
            s0.x += a0.x; s0.y += a0.y;
        }
        s0.x += s1.x; s0.y += s1.y;

        if (PASS == 2) {
            float sc = g_dinv[node];
            float2 bb = __ldg(&reinterpret_cast<const float2*>(b)[lane]);
            float2 o;
            o.x = sc * s0.x + bb.x;
            o.y = sc * s0.y + bb.y;
            reinterpret_cast<float2*>(outp)[(size_t)node * 32 + lane] = o;
        } else {
            float sc = g_dinv2[node];
            uout[(size_t)node * 32 + lane] = __floats2half2_rn(sc * s0.x, sc * s0.y);
        }
    }
}

// ---------------------------------------------------------------------------
__global__ void __launch_bounds__(TPB, 2)
sgc_mono(const float* __restrict__ x, const void* __restrict__ ei, int E,
         const float* __restrict__ W, const float* __restrict__ b,
         float* __restrict__ out) {
    __shared__ __align__(16) char s_mem[32768];   // Ws (GEMM) / bs (scan)
    float* Ws = reinterpret_cast<float*>(s_mem);              // [128*64]
    int*   bs = reinterpret_cast<int*>(s_mem);                // scan scratch

    const int tid = threadIdx.x;
    const int bid = blockIdx.x;
    const int gthread = bid * TPB + tid;
    const int gstride = GRID * TPB;

    // ---- Phase 0: zero histogram + dtype detect ---------------------------
    for (int i = gthread; i < N_NODES; i += gstride) g_cnt[i] = 0;
    if (bid == 0) {
        __shared__ int any;
        if (tid == 0) any = 0;
        __syncthreads();
        const int* ei32 = (const int*)ei;
        for (int i = tid; i < 1024; i += TPB)
            if (ei32[2 * i + 1] != 0) any = 1;   // benign race
        __syncthreads();
        if (tid == 0) g_is64 = (any == 0) ? 1 : 0;
    }
    grid_barrier(0);

    // ---- Phase 1: degree histogram ----------------------------------------
    for (int e = gthread; e < E; e += gstride) {
        unsigned t = (unsigned)edge_idx(ei, E, 1, e);
        if (t < N_NODES) atomicAdd(&g_cnt[t], 1);
    }
    grid_barrier(1);

    // ---- Phase 2: per-block chunk sums ------------------------------------
    {
        int beg = bid * CHUNK;
        int len = N_NODES - beg; if (len > CHUNK) len = CHUNK; if (len < 0) len = 0;
        int v = (tid < len) ? g_cnt[beg + tid] : 0;
        bs[tid] = v;
        __syncthreads();
        for (int off = TPB / 2; off > 0; off >>= 1) {
            if (tid < off) bs[tid] += bs[tid + off];
            __syncthreads();
        }
        if (tid == 0) g_blk[bid] = bs[0];
    }
    grid_barrier(2);

    // ---- Phase 3: block 0 scans the 296 block sums ------------------------
    if (bid == 0) {
        int v = (tid < GRID) ? g_blk[tid] : 0;
        bs[tid] = v;
        __syncthreads();
        for (int off = 1; off < TPB; off <<= 1) {    // Hillis-Steele inclusive
            int p = (tid >= off) ? bs[tid - off] : 0;
            __syncthreads();
            bs[tid] += p;
            __syncthreads();
        }
        if (tid < GRID) g_blk[tid] = bs[tid] - v;    // exclusive
        if (tid == 0) g_off[N_NODES] = bs[TPB - 1];
    }
    grid_barrier(3);

    // ---- Phase 4: per-chunk exclusive scan + dinv/dinv2 --------------------
    {
        int beg = bid * CHUNK;
        int len = N_NODES - beg; if (len > CHUNK) len = CHUNK; if (len < 0) len = 0;
        int c = (tid < len) ? g_cnt[beg + tid] : 0;
        bs[tid] = c;
        __syncthreads();
        for (int off = 1; off < TPB; off <<= 1) {
            int p = (tid >= off) ? bs[tid - off] : 0;
            __syncthreads();
            bs[tid] += p;
            __syncthreads();
        }
        if (tid < len) {
            int excl = g_blk[bid] + bs[tid] - c;
            int i = beg + tid;
            g_off[i] = excl;
            g_cur[i] = excl;
            float deg = (float)c + 1.0f;
            g_dinv[i]  = rsqrtf(deg);
            g_dinv2[i] = 1.0f / deg;
        }
    }
    grid_barrier(4);

    // ---- Phase 5: scatter (CSR fill) then register-tiled GEMM ---------------
    for (int e = gthread; e < E; e += gstride) {
        unsigned t = (unsigned)edge_idx(ei, E, 1, e);
        unsigned s = (unsigned)edge_idx(ei, E, 0, e);
        if (t >= N_NODES || s >= N_NODES) continue;
        int pos = atomicAdd(&g_cur[t], 1);
        if (pos < E_MAX) g_adj[pos] = (int)s;
    }
    // GEMM: u0[i,:] = dinv[i] * (x[i,:] @ W^T), stored fp16.
    // Warp owns 4 rows; lane owns col pair (2*cp, 2*cp+1). x read from global
    // (broadcast float4 per row); one Ws2 LDS feeds 8 FMAs.
    {
        __syncthreads();   // bs scratch -> Ws reuse
        for (int i = tid; i < 2048; i += TPB) {
            float4 w4 = __ldg(&reinterpret_cast<const float4*>(W)[i]);
            int c = i >> 5;
            int k = (i & 31) << 2;
            Ws[(k + 0) * 64 + c] = w4.x;
            Ws[(k + 1) * 64 + c] = w4.y;
            Ws[(k + 2) * 64 + c] = w4.z;
            Ws[(k + 3) * 64 + c] = w4.w;
        }
        __syncthreads();
        const float2* Ws2 = reinterpret_cast<const float2*>(Ws);  // [k][32] pairs
        const float4* x4  = reinterpret_cast<const float4*>(x);
        int cp  = tid & 31;       // column pair
        int wrp = tid >> 5;       // 0..15, 4 rows each -> 64 rows per block-iter

        for (int rb = bid * 64; rb < N_NODES; rb += GRID * 64) {
            int r0 = rb + wrp * 4;
            if (r0 >= N_NODES) continue;
            // clamp row indices for safe loads; stores are predicated
            int r1 = (r0 + 1 < N_NODES) ? r0 + 1 : N_NODES - 1;
            int r2 = (r0 + 2 < N_NODES) ? r0 + 2 : N_NODES - 1;
            int r3 = (r0 + 3 < N_NODES) ? r0 + 3 : N_NODES - 1;

            float2 acc0 = make_float2(0.f, 0.f);
            float2 acc1 = make_float2(0.f, 0.f);
            float2 acc2 = make_float2(0.f, 0.f);
            float2 acc3 = make_float2(0.f, 0.f);

            #pragma unroll 2
            for (int i = 0; i < 32; i++) {
                float4 xv0 = __ldg(&x4[(size_t)r0 * 32 + i]);
                float4 xv1 = __ldg(&x4[(size_t)r1 * 32 + i]);
                float4 xv2 = __ldg(&x4[(size_t)r2 * 32 + i]);
                float4 xv3 = __ldg(&x4[(size_t)r3 * 32 + i]);
                float2 w;
                w = Ws2[(i * 4 + 0) * 32 + cp];
                acc0.x = fmaf(xv0.x, w.x, acc0.x); acc0.y = fmaf(xv0.x, w.y, acc0.y);
                acc1.x = fmaf(xv1.x, w.x, acc1.x); acc1.y = fmaf(xv1.x, w.y, acc1.y);
                acc2.x = fmaf(xv2.x, w.x, acc2.x); acc2.y = fmaf(xv2.x, w.y, acc2.y);
                acc3.x = fmaf(xv3.x, w.x, acc3.x); acc3.y = fmaf(xv3.x, w.y, acc3.y);
                w = Ws2[(i * 4 + 1) * 32 + cp];
                acc0.x = fmaf(xv0.y, w.x, acc0.x); acc0.y = fmaf(xv0.y, w.y, acc0.y);
                acc1.x = fmaf(xv1.y, w.x, acc1.x); acc1.y = fmaf(xv1.y, w.y, acc1.y);
                acc2.x = fmaf(xv2.y, w.x, acc2.x); acc2.y = fmaf(xv2.y, w.y, acc2.y);
                acc3.x = fmaf(xv3.y, w.x, acc3.x); acc3.y = fmaf(xv3.y, w.y, acc3.y);
                w = Ws2[(i * 4 + 2) * 32 + cp];
                acc0.x = fmaf(xv0.z, w.x, acc0.x); acc0.y = fmaf(xv0.z, w.y, acc0.y);
                acc1.x = fmaf(xv1.z, w.x, acc1.x); acc1.y = fmaf(xv1.z, w.y, acc1.y);
                acc2.x = fmaf(xv2.z, w.x, acc2.x); acc2.y = fmaf(xv2.z, w.y, acc2.y);
                acc3.x = fmaf(xv3.z, w.x, acc3.x); acc3.y = fmaf(xv3.z, w.y, acc3.y);
                w = Ws2[(i * 4 + 3) * 32 + cp];
                acc0.x = fmaf(xv0.w, w.x, acc0.x); acc0.y = fmaf(xv0.w, w.y, acc0.y);
                acc1.x = fmaf(xv1.w, w.x, acc1.x); acc1.y = fmaf(xv1.w, w.y, acc1.y);
                acc2.x = fmaf(xv2.w, w.x, acc2.x); acc2.y = fmaf(xv2.w, w.y, acc2.y);
                acc3.x = fmaf(xv3.w, w.x, acc3.x); acc3.y = fmaf(xv3.w, w.y, acc3.y);
            }

            float sc0 = g_dinv[r0];
            g_uh[(size_t)r0 * 32 + cp] = __floats2half2_rn(sc0 * acc0.x, sc0 * acc0.y);
            if (r0 + 1 < N_NODES) {
                float sc = g_dinv[r1];
                g_uh[(size_t)r1 * 32 + cp] = __floats2half2_rn(sc * acc1.x, sc * acc1.y);
            }
            if (r0 + 2 < N_NODES) {
                float sc = g_dinv[r2];
                g_uh[(size_t)r2 * 32 + cp] = __floats2half2_rn(sc * acc2.x, sc * acc2.y);
            }
            if (r0 + 3 < N_NODES) {
                float sc = g_dinv[r3];
                g_uh[(size_t)r3 * 32 + cp] = __floats2half2_rn(sc * acc3.x, sc * acc3.y);
            }
        }
    }
    grid_barrier(5);

    // ---- Phases 6-8: three gather hops -------------------------------------
    hop_phase<0>(nullptr, b);
    grid_barrier(6);
    hop_phase<1>(nullptr, b);
    grid_barrier(7);
    hop_phase<2>(out, b);
}

// ---------------------------------------------------------------------------
extern "C" void kernel_launch(void* const* d_in, const int* in_sizes, int n_in,
                              void* d_out, int out_size) {
    const float* x  = (const float*)d_in[0];   // [100000,128]
    const void*  ei = d_in[1];                 // [2, E] int32 or int64
    const float* W  = (const float*)d_in[2];   // [64,128]
    const float* b  = (const float*)d_in[3];   // [64]
    float* out = (float*)d_out;

    const int E = in_sizes[1] / 2;             // 1,600,000

    sgc_mono<<<GRID, TPB>>>(x, ei, E, W, b, out);
}

// round 12
// speedup vs baseline: 1.6518x; 1.3144x over previous
#include <cuda_runtime.h>
#include <cuda_fp16.h>
#include <cstdint>

#define N_NODES 100000
#define FEAT    64
#define NF      (N_NODES * FEAT)
#define E_MAX   1700000
#define GRID    296            // 2 blocks/SM on 148 SMs (co-resident, barrier-safe)
#define TPB     512
#define CHUNK   338            // ceil(N_NODES / GRID)
#define NBAR    8
#define NTILES  (N_NODES / 16) // 6250 row-tiles of 16 (100000 = 6250*16 exactly)

// Scratch: device globals (no allocations allowed). Zero-initialized.
__device__ __align__(16) __half2 g_uh[NF / 2];   // fp16 feature buffers
__device__ __align__(16) __half2 g_uh2[NF / 2];
__device__ int   g_cnt[N_NODES];
__device__ int   g_off[N_NODES + 1];
__device__ int   g_cur[N_NODES];
__device__ int   g_adj[E_MAX];
__device__ int   g_blk[GRID];
__device__ float g_dinv[N_NODES];    // (deg)^{-1/2}, deg includes self-loop
__device__ float g_dinv2[N_NODES];   // (deg)^{-1}
__device__ int   g_is64;             // 1 if edge_index is int64, 0 if int32
// Grid barrier state; slot k's flag resets at release of slot k+1 (circular),
// so state returns to a reusable configuration every launch (replay-safe).
__device__ unsigned      g_bar_cnt[NBAR];
__device__ volatile int  g_bar_flag[NBAR];

// ---------------------------------------------------------------------------
__device__ __forceinline__ void grid_barrier(int slot) {
    __syncthreads();
    if (threadIdx.x == 0) {
        __threadfence();
        unsigned old = atomicAdd(&g_bar_cnt[slot], 1u);
        if (old == GRID - 1) {
            g_bar_cnt[slot] = 0;
            g_bar_flag[(slot + NBAR - 1) % NBAR] = 0;
            __threadfence();
            g_bar_flag[slot] = 1;
        } else {
            while (g_bar_flag[slot] == 0) { __nanosleep(64); }
            __threadfence();
        }
    }
    __syncthreads();
}

__device__ __forceinline__ int edge_idx(const void* ei, int E, int half, int e) {
    if (g_is64) return (int)((const long long*)ei)[(size_t)half * E + e];
    return ((const int*)ei)[(size_t)half * E + e];
}

__device__ __forceinline__ unsigned f2h2(float a, float b) {
    __half2 h = __floats2half2_rn(a, b);
    return *reinterpret_cast<unsigned*>(&h);
}

// ---------------------------------------------------------------------------
// Gather hop: ONE WARP per node; lane owns feature pair (2*lane, 2*lane+1).
// One edge gather = 32 lanes x 4B = 128B = single cache line.
template <int PASS>
__device__ void hop_phase(float* __restrict__ outp, const float* __restrict__ b) {
    const __half2* uin = (PASS == 1) ? g_uh2 : g_uh;
    __half2* uout = (PASS == 0) ? g_uh2 : g_uh;
    int lane = threadIdx.x & 31;
    int w    = threadIdx.x >> 5;         // 0..15 warps per block

    for (int node = blockIdx.x * 16 + w; node < N_NODES; node += GRID * 16) {
        int d   = g_off[node];
        int end = g_off[node + 1];

        float2 s0 = __half22float2(uin[(size_t)node * 32 + lane]);  // self
        float2 s1 = make_float2(0.f, 0.f);

        for (; d + 3 < end; d += 4) {
            int j0 = __ldg(&g_adj[d + 0]);
            int j1 = __ldg(&g_adj[d + 1]);
            int j2 = __ldg(&g_adj[d + 2]);
            int j3 = __ldg(&g_adj[d + 3]);
            float2 a0 = __half22float2(__ldg(&uin[(size_t)j0 * 32 + lane]));
            float2 a1 = __half22float2(__ldg(&uin[(size_t)j1 * 32 + lane]));
            float2 a2 = __half22float2(__ldg(&uin[(size_t)j2 * 32 + lane]));
            float2 a3 = __half22float2(__ldg(&uin[(size_t)j3 * 32 + lane]));
            s0.x += a0.x + a1.x;  s0.y += a0.y + a1.y;
            s1.x += a2.x + a3.x;  s1.y += a2.y + a3.y;
        }
        for (; d < end; d++) {
            int j0 = __ldg(&g_adj[d]);
            float2 a0 = __half22float2(__ldg(&uin[(size_t)j0 * 32 + lane]));
            s0.x += a0.x; s0.y += a0.y;
        }
        s0.x += s1.x; s0.y += s1.y;

        if (PASS == 2) {
            float sc = g_dinv[node];
            float2 bb = __ldg(&reinterpret_cast<const float2*>(b)[lane]);
            float2 o;
            o.x = sc * s0.x + bb.x;
            o.y = sc * s0.y + bb.y;
            reinterpret_cast<float2*>(outp)[(size_t)node * 32 + lane] = o;
        } else {
            float sc = g_dinv2[node];
            uout[(size_t)node * 32 + lane] = __floats2half2_rn(sc * s0.x, sc * s0.y);
        }
    }
}

// ---------------------------------------------------------------------------
__global__ void __launch_bounds__(TPB, 2)
sgc_mono(const float* __restrict__ x, const void* __restrict__ ei, int E,
         const float* __restrict__ W, const float* __restrict__ b,
         float* __restrict__ out) {
    __shared__ __align__(16) char s_mem[17472];   // Wh2 (GEMM, 64*68*4B) / bs (scan)
    int* bs = reinterpret_cast<int*>(s_mem);      // scan scratch (2048B)

    const int tid = threadIdx.x;
    const int bid = blockIdx.x;
    const int gthread = bid * TPB + tid;
    const int gstride = GRID * TPB;

    // ---- Phase 0: zero histogram + dtype detect ---------------------------
    for (int i = gthread; i < N_NODES; i += gstride) g_cnt[i] = 0;
    if (bid == 0) {
        __shared__ int any;
        if (tid == 0) any = 0;
        __syncthreads();
        const int* ei32 = (const int*)ei;
        for (int i = tid; i < 1024; i += TPB)
            if (ei32[2 * i + 1] != 0) any = 1;   // benign race
        __syncthreads();
        if (tid == 0) g_is64 = (any == 0) ? 1 : 0;
    }
    grid_barrier(0);

    // ---- Phase 1: degree histogram ----------------------------------------
    for (int e = gthread; e < E; e += gstride) {
        unsigned t = (unsigned)edge_idx(ei, E, 1, e);
        if (t < N_NODES) atomicAdd(&g_cnt[t], 1);
    }
    grid_barrier(1);

    // ---- Phase 2: per-block chunk sums ------------------------------------
    {
        int beg = bid * CHUNK;
        int len = N_NODES - beg; if (len > CHUNK) len = CHUNK; if (len < 0) len = 0;
        int v = (tid < len) ? g_cnt[beg + tid] : 0;
        bs[tid] = v;
        __syncthreads();
        for (int off = TPB / 2; off > 0; off >>= 1) {
            if (tid < off) bs[tid] += bs[tid + off];
            __syncthreads();
        }
        if (tid == 0) g_blk[bid] = bs[0];
    }
    grid_barrier(2);

    // ---- Phase 3: block 0 scans the 296 block sums ------------------------
    if (bid == 0) {
        int v = (tid < GRID) ? g_blk[tid] : 0;
        bs[tid] = v;
        __syncthreads();
        for (int off = 1; off < TPB; off <<= 1) {    // Hillis-Steele inclusive
            int p = (tid >= off) ? bs[tid - off] : 0;
            __syncthreads();
            bs[tid] += p;
            __syncthreads();
        }
        if (tid < GRID) g_blk[tid] = bs[tid] - v;    // exclusive
        if (tid == 0) g_off[N_NODES] = bs[TPB - 1];
    }
    grid_barrier(3);

    // ---- Phase 4: per-chunk exclusive scan + dinv/dinv2 --------------------
    {
        int beg = bid * CHUNK;
        int len = N_NODES - beg; if (len > CHUNK) len = CHUNK; if (len < 0) len = 0;
        int c = (tid < len) ? g_cnt[beg + tid] : 0;
        bs[tid] = c;
        __syncthreads();
        for (int off = 1; off < TPB; off <<= 1) {
            int p = (tid >= off) ? bs[tid - off] : 0;
            __syncthreads();
            bs[tid] += p;
            __syncthreads();
        }
        if (tid < len) {
            int excl = g_blk[bid] + bs[tid] - c;
            int i = beg + tid;
            g_off[i] = excl;
            g_cur[i] = excl;
            float deg = (float)c + 1.0f;
            g_dinv[i]  = rsqrtf(deg);
            g_dinv2[i] = 1.0f / deg;
        }
    }
    grid_barrier(4);

    // ---- Phase 5: scatter (CSR fill) then tensor-core GEMM ------------------
    for (int e = gthread; e < E; e += gstride) {
        unsigned t = (unsigned)edge_idx(ei, E, 1, e);
        unsigned s = (unsigned)edge_idx(ei, E, 0, e);
        if (t >= N_NODES || s >= N_NODES) continue;
        int pos = atomicAdd(&g_cur[t], 1);
        if (pos < E_MAX) g_adj[pos] = (int)s;
    }
    // GEMM: u0[i,:] = dinv[i] * (x[i,:] @ W^T), stored fp16.
    // HMMA m16n8k16: warp computes a 16x64 tile (8 k-steps x 8 n-tiles),
    // fp16 inputs (converted on the fly), fp32 accumulate.
    {
        __syncthreads();   // bs scratch -> Wh2 reuse
        __half2* Wh2 = reinterpret_cast<__half2*>(s_mem);   // [n][kp], stride 68
        for (int i = tid; i < 64 * 64; i += TPB) {          // 4096 W half2-pairs
            int n = i >> 6, kp = i & 63;
            float2 wv = __ldg(&reinterpret_cast<const float2*>(W)[(size_t)n * 64 + kp]);
            Wh2[n * 68 + kp] = __floats2half2_rn(wv.x, wv.y);
        }
        __syncthreads();

        const float2* x2 = reinterpret_cast<const float2*>(x);
        int lane = tid & 31;
        int wrp  = tid >> 5;
        int qp = lane >> 2;     // lane/4: A-row within 8-group / B col within 8
        int rp = lane & 3;      // lane%4: k-pair selector / D col-pair

        for (int tile = bid * 16 + wrp; tile < NTILES; tile += GRID * 16) {
            int r0 = tile * 16 + qp;     // this thread's rows: r0 and r0+8

            float acc[8][4];
            #pragma unroll
            for (int nt = 0; nt < 8; nt++) {
                acc[nt][0] = acc[nt][1] = acc[nt][2] = acc[nt][3] = 0.f;
            }

            #pragma unroll
            for (int ks = 0; ks < 8; ks++) {
                int kb = ks * 8 + rp;    // float2 index within the 64-pair row
                float2 va0 = __ldg(&x2[(size_t)r0 * 64 + kb]);
                float2 va1 = __ldg(&x2[(size_t)(r0 + 8) * 64 + kb]);
                float2 va2 = __ldg(&x2[(size_t)r0 * 64 + kb + 4]);
                float2 va3 = __ldg(&x2[(size_t)(r0 + 8) * 64 + kb + 4]);
                unsigned a0 = f2h2(va0.x, va0.y);
                unsigned a1 = f2h2(va1.x, va1.y);
                unsigned a2 = f2h2(va2.x, va2.y);
                unsigned a3 = f2h2(va3.x, va3.y);

                #pragma unroll
                for (int nt = 0; nt < 8; nt++) {
                    int col = nt * 8 + qp;
                    __half2 b0h = Wh2[col * 68 + ks * 8 + rp];
                    __half2 b1h = Wh2[col * 68 + ks * 8 + rp + 4];
                    unsigned b0 = *reinterpret_cast<unsigned*>(&b0h);
                    unsigned b1 = *reinterpret_cast<unsigned*>(&b1h);
                    asm volatile(
                        "mma.sync.aligned.m16n8k16.row.col.f32.f16.f16.f32 "
                        "{%0,%1,%2,%3}, {%4,%5,%6,%7}, {%8,%9}, {%0,%1,%2,%3};"
                        : "+f"(acc[nt][0]), "+f"(acc[nt][1]),
                          "+f"(acc[nt][2]), "+f"(acc[nt][3])
                        : "r"(a0), "r"(a1), "r"(a2), "r"(a3), "r"(b0), "r"(b1));
                }
            }

            float sc0 = g_dinv[r0];
            float sc1 = g_dinv[r0 + 8];
            #pragma unroll
            for (int nt = 0; nt < 8; nt++) {
                g_uh[(size_t)r0 * 32 + nt * 4 + rp] =
                    __floats2half2_rn(sc0 * acc[nt][0], sc0 * acc[nt][1]);
                g_uh[(size_t)(r0 + 8) * 32 + nt * 4 + rp] =
                    __floats2half2_rn(sc1 * acc[nt][2], sc1 * acc[nt][3]);
            }
        }
    }
    grid_barrier(5);

    // ---- Phases 6-8: three gather hops -------------------------------------
    hop_phase<0>(nullptr, b);
    grid_barrier(6);
    hop_phase<1>(nullptr, b);
    grid_barrier(7);
    hop_phase<2>(out, b);
}

// ---------------------------------------------------------------------------
extern "C" void kernel_launch(void* const* d_in, const int* in_sizes, int n_in,
                              void* d_out, int out_size) {
    const float* x  = (const float*)d_in[0];   // [100000,128]
    const void*  ei = d_in[1];                 // [2, E] int32 or int64
    const float* W  = (const float*)d_in[2];   // [64,128]
    const float* b  = (const float*)d_in[3];   // [64]
    float* out = (float*)d_out;

    const int E = in_sizes[1] / 2;             // 1,600,000

    sgc_mono<<<GRID, TPB>>>(x, ei, E, W, b, out);
}

// round 13
// speedup vs baseline: 1.7018x; 1.0303x over previous
#include <cuda_runtime.h>
#include <cuda_fp16.h>
#include <cstdint>

#define N_NODES 100000
#define FEAT    64
#define NF      (N_NODES * FEAT)
#define E_MAX   1700000
#define GRID    296            // 2 blocks/SM on 148 SMs (co-resident, barrier-safe)
#define TPB     512
#define CHUNK   338            // ceil(N_NODES / GRID)
#define NBAR    7
#define NTILES  (N_NODES / 16) // 6250 row-tiles of 16

// Scratch: device globals (no allocations allowed). Zero-initialized.
// g_cnt invariant: zero at entry to every launch (re-zeroed in phase 4).
__device__ __align__(16) __half2 g_uh[NF / 2];   // fp16 feature buffers
__device__ __align__(16) __half2 g_uh2[NF / 2];
__device__ int   g_cnt[N_NODES];
__device__ int   g_off[N_NODES + 1];
__device__ int   g_cur[N_NODES];
__device__ int   g_adj[E_MAX];
__device__ int   g_blk[GRID];
__device__ float g_dinv[N_NODES];    // (deg)^{-1/2}, deg includes self-loop
__device__ float g_dinv2[N_NODES];   // (deg)^{-1}
// Grid barrier state; slot k's flag resets at release of slot k+1 (circular
// over NBAR used slots), so state self-cleans every launch (replay-safe).
__device__ unsigned      g_bar_cnt[NBAR];
__device__ volatile int  g_bar_flag[NBAR];

// ---------------------------------------------------------------------------
__device__ __forceinline__ void grid_barrier(int slot) {
    __syncthreads();
    if (threadIdx.x == 0) {
        __threadfence();
        unsigned old = atomicAdd(&g_bar_cnt[slot], 1u);
        if (old == GRID - 1) {
            g_bar_cnt[slot] = 0;
            g_bar_flag[(slot + NBAR - 1) % NBAR] = 0;
            __threadfence();
            g_bar_flag[slot] = 1;
        } else {
            while (g_bar_flag[slot] == 0) { __nanosleep(64); }
            __threadfence();
        }
    }
    __syncthreads();
}

__device__ __forceinline__ int edge_idx(const void* ei, int E, int half, int e,
                                        int is64) {
    if (is64) return (int)((const long long*)ei)[(size_t)half * E + e];
    return ((const int*)ei)[(size_t)half * E + e];
}

__device__ __forceinline__ unsigned f2h2(float a, float b) {
    __half2 h = __floats2half2_rn(a, b);
    return *reinterpret_cast<unsigned*>(&h);
}
__device__ __forceinline__ float2 h2f2(unsigned u) {
    __half2 h = *reinterpret_cast<__half2*>(&u);
    return __half22float2(h);
}

// ---------------------------------------------------------------------------
// Gather hop: ONE WARP per node, split into two 16-lane halves that process
// interleaved edges. Lane hl of each half owns features [4hl..4hl+3] (uint2 =
// 4 fp16). One gather instruction moves TWO edges (2 x 128B lines). Final
// shfl_xor(16) combines the halves.
template <int PASS>
__device__ void hop_phase(float* __restrict__ outp, const float* __restrict__ b) {
    const uint2* uin = reinterpret_cast<const uint2*>((PASS == 1) ? g_uh2 : g_uh);
    uint2* uout = reinterpret_cast<uint2*>((PASS == 0) ? g_uh2 : g_uh);
    int lane = threadIdx.x & 31;
    int half = lane >> 4;
    int hl   = lane & 15;
    int w    = threadIdx.x >> 5;         // 0..15 warps per block

    for (int node = blockIdx.x * 16 + w; node < N_NODES; node += GRID * 16) {
        int d   = g_off[node];
        int end = g_off[node + 1];

        float4 s0 = make_float4(0.f, 0.f, 0.f, 0.f);
        float4 s1 = make_float4(0.f, 0.f, 0.f, 0.f);
        if (half == 0) {                 // self-loop term counted once
            uint2 v = uin[(size_t)node * 16 + hl];
            float2 f0 = h2f2(v.x), f1 = h2f2(v.y);
            s0.x = f0.x; s0.y = f0.y; s0.z = f1.x; s0.w = f1.y;
        }

        int d2 = d + half;               // this half's edge stream (stride 2)
        for (; d2 + 2 < end; d2 += 4) {  // 2 edges per iter per half
            int j0 = __ldg(&g_adj[d2]);
            int j1 = __ldg(&g_adj[d2 + 2]);
            uint2 v0 = __ldg(&uin[(size_t)j0 * 16 + hl]);
            uint2 v1 = __ldg(&uin[(size_t)j1 * 16 + hl]);
            float2 a0 = h2f2(v0.x), a1 = h2f2(v0.y);
            float2 c0 = h2f2(v1.x), c1 = h2f2(v1.y);
            s0.x += a0.x; s0.y += a0.y; s0.z += a1.x; s0.w += a1.y;
            s1.x += c0.x; s1.y += c0.y; s1.z += c1.x; s1.w += c1.y;
        }
        if (d2 < end) {
            int j0 = __ldg(&g_adj[d2]);
            uint2 v0 = __ldg(&uin[(size_t)j0 * 16 + hl]);
            float2 a0 = h2f2(v0.x), a1 = h2f2(v0.y);
            s0.x += a0.x; s0.y += a0.y; s0.z += a1.x; s0.w += a1.y;
        }
        s0.x += s1.x; s0.y += s1.y; s0.z += s1.z; s0.w += s1.w;

        // combine halves
        s0.x += __shfl_xor_sync(0xFFFFFFFFu, s0.x, 16);
        s0.y += __shfl_xor_sync(0xFFFFFFFFu, s0.y, 16);
        s0.z += __shfl_xor_sync(0xFFFFFFFFu, s0.z, 16);
        s0.w += __shfl_xor_sync(0xFFFFFFFFu, s0.w, 16);

        if (half == 0) {
            if (PASS == 2) {
                float sc = g_dinv[node];
                float4 bb = __ldg(&reinterpret_cast<const float4*>(b)[hl]);
                float4 o;
                o.x = sc * s0.x + bb.x;
                o.y = sc * s0.y + bb.y;
                o.z = sc * s0.z + bb.z;
                o.w = sc * s0.w + bb.w;
                reinterpret_cast<float4*>(outp)[(size_t)node * 16 + hl] = o;
            } else {
                float sc = g_dinv2[node];
                uint2 o;
                o.x = f2h2(sc * s0.x, sc * s0.y);
                o.y = f2h2(sc * s0.z, sc * s0.w);
                uout[(size_t)node * 16 + hl] = o;
            }
        }
    }
}

// ---------------------------------------------------------------------------
__global__ void __launch_bounds__(TPB, 2)
sgc_mono(const float* __restrict__ x, const void* __restrict__ ei, int E,
         const float* __restrict__ W, const float* __restrict__ b,
         float* __restrict__ out) {
    __shared__ __align__(16) char s_mem[17472];   // Wh2 (GEMM) / bs (scan)
    int* bs = reinterpret_cast<int*>(s_mem);      // scan scratch (2048B)

    const int tid = threadIdx.x;
    const int bid = blockIdx.x;
    const int gthread = bid * TPB + tid;
    const int gstride = GRID * TPB;

    // ---- Block-local dtype detect (no grid dependency) ---------------------
    int any = 0;
    {
        const int* ei32 = (const int*)ei;
        for (int i = tid; i < 1024; i += TPB)
            any |= (ei32[2 * i + 1] != 0);
    }
    const int is64 = (__syncthreads_or(any) == 0);

    // ---- Phase 1: degree histogram (g_cnt is zero at entry) ----------------
    for (int e = gthread; e < E; e += gstride) {
        unsigned t = (unsigned)edge_idx(ei, E, 1, e, is64);
        if (t < N_NODES) atomicAdd(&g_cnt[t], 1);
    }
    grid_barrier(0);

    // ---- Phase 2: per-block chunk sums ------------------------------------
    {
        int beg = bid * CHUNK;
        int len = N_NODES - beg; if (len > CHUNK) len = CHUNK; if (len < 0) len = 0;
        int v = (tid < len) ? g_cnt[beg + tid] : 0;
        bs[tid] = v;
        __syncthreads();
        for (int off = TPB / 2; off > 0; off >>= 1) {
            if (tid < off) bs[tid] += bs[tid + off];
            __syncthreads();
        }
        if (tid == 0) g_blk[bid] = bs[0];
    }
    grid_barrier(1);

    // ---- Phase 3: block 0 scans the 296 block sums ------------------------
    if (bid == 0) {
        int v = (tid < GRID) ? g_blk[tid] : 0;
        bs[tid] = v;
        __syncthreads();
        for (int off = 1; off < TPB; off <<= 1) {    // Hillis-Steele inclusive
            int p = (tid >= off) ? bs[tid - off] : 0;
            __syncthreads();
            bs[tid] += p;
            __syncthreads();
        }
        if (tid < GRID) g_blk[tid] = bs[tid] - v;    // exclusive
        if (tid == 0) g_off[N_NODES] = bs[TPB - 1];
    }
    grid_barrier(2);

    // ---- Phase 4: per-chunk exclusive scan + dinv/dinv2 + g_cnt re-zero ----
    {
        int beg = bid * CHUNK;
        int len = N_NODES - beg; if (len > CHUNK) len = CHUNK; if (len < 0) len = 0;
        int c = (tid < len) ? g_cnt[beg + tid] : 0;
        bs[tid] = c;
        __syncthreads();
        for (int off = 1; off < TPB; off <<= 1) {
            int p = (tid >= off) ? bs[tid - off] : 0;
            __syncthreads();
            bs[tid] += p;
            __syncthreads();
        }
        if (tid < len) {
            int excl = g_blk[bid] + bs[tid] - c;
            int i = beg + tid;
            g_off[i] = excl;
            g_cur[i] = excl;
            g_cnt[i] = 0;                      // restore zero invariant
            float deg = (float)c + 1.0f;
            g_dinv[i]  = rsqrtf(deg);
            g_dinv2[i] = 1.0f / deg;
        }
    }
    grid_barrier(3);

    // ---- Phase 5: scatter (CSR fill) then tensor-core GEMM ------------------
    for (int e = gthread; e < E; e += gstride) {
        unsigned t = (unsigned)edge_idx(ei, E, 1, e, is64);
        unsigned s = (unsigned)edge_idx(ei, E, 0, e, is64);
        if (t >= N_NODES || s >= N_NODES) continue;
        int pos = atomicAdd(&g_cur[t], 1);
        if (pos < E_MAX) g_adj[pos] = (int)s;
    }
    // GEMM: u0[i,:] = dinv[i] * (x[i,:] @ W^T), stored fp16.
    // HMMA m16n8k16: warp computes a 16x64 tile, fp32 accumulate.
    {
        __syncthreads();   // bs scratch -> Wh2 reuse
        __half2* Wh2 = reinterpret_cast<__half2*>(s_mem);   // [n][kp], stride 68
        for (int i = tid; i < 64 * 64; i += TPB) {          // 4096 W half2-pairs
            int n = i >> 6, kp = i & 63;
            float2 wv = __ldg(&reinterpret_cast<const float2*>(W)[(size_t)n * 64 + kp]);
            Wh2[n * 68 + kp] = __floats2half2_rn(wv.x, wv.y);
        }
        __syncthreads();

        const float2* x2 = reinterpret_cast<const float2*>(x);
        int lane = tid & 31;
        int wrp  = tid >> 5;
        int qp = lane >> 2;     // lane/4
        int rp = lane & 3;      // lane%4

        for (int tile = bid * 16 + wrp; tile < NTILES; tile += GRID * 16) {
            int r0 = tile * 16 + qp;     // this thread's rows: r0 and r0+8

            float acc[8][4];
            #pragma unroll
            for (int nt = 0; nt < 8; nt++)
                acc[nt][0] = acc[nt][1] = acc[nt][2] = acc[nt][3] = 0.f;

            #pragma unroll
            for (int ks = 0; ks < 8; ks++) {
                int kb = ks * 8 + rp;
                float2 va0 = __ldg(&x2[(size_t)r0 * 64 + kb]);
                float2 va1 = __ldg(&x2[(size_t)(r0 + 8) * 64 + kb]);
                float2 va2 = __ldg(&x2[(size_t)r0 * 64 + kb + 4]);
                float2 va3 = __ldg(&x2[(size_t)(r0 + 8) * 64 + kb + 4]);
                unsigned a0 = f2h2(va0.x, va0.y);
                unsigned a1 = f2h2(va1.x, va1.y);
                unsigned a2 = f2h2(va2.x, va2.y);
                unsigned a3 = f2h2(va3.x, va3.y);

                #pragma unroll
                for (int nt = 0; nt < 8; nt++) {
                    int col = nt * 8 + qp;
                    __half2 b0h = Wh2[col * 68 + ks * 8 + rp];
                    __half2 b1h = Wh2[col * 68 + ks * 8 + rp + 4];
                    unsigned b0 = *reinterpret_cast<unsigned*>(&b0h);
                    unsigned b1 = *reinterpret_cast<unsigned*>(&b1h);
                    asm volatile(
                        "mma.sync.aligned.m16n8k16.row.col.f32.f16.f16.f32 "
                        "{%0,%1,%2,%3}, {%4,%5,%6,%7}, {%8,%9}, {%0,%1,%2,%3};"
                        : "+f"(acc[nt][0]), "+f"(acc[nt][1]),
                          "+f"(acc[nt][2]), "+f"(acc[nt][3])
                        : "r"(a0), "r"(a1), "r"(a2), "r"(a3), "r"(b0), "r"(b1));
                }
            }

            float sc0 = g_dinv[r0];
            float sc1 = g_dinv[r0 + 8];
            #pragma unroll
            for (int nt = 0; nt < 8; nt++) {
                g_uh[(size_t)r0 * 32 + nt * 4 + rp] =
                    __floats2half2_rn(sc0 * acc[nt][0], sc0 * acc[nt][1]);
                g_uh[(size_t)(r0 + 8) * 32 + nt * 4 + rp] =
                    __floats2half2_rn(sc1 * acc[nt][2], sc1 * acc[nt][3]);
            }
        }
    }
    grid_barrier(4);

    // ---- Phases 6-8: three gather hops -------------------------------------
    hop_phase<0>(nullptr, b);
    grid_barrier(5);
    hop_phase<1>(nullptr, b);
    grid_barrier(6);
    hop_phase<2>(out, b);
}

// ---------------------------------------------------------------------------
extern "C" void kernel_launch(void* const* d_in, const int* in_sizes, int n_in,
                              void* d_out, int out_size) {
    const float* x  = (const float*)d_in[0];   // [100000,128]
    const void*  ei = d_in[1];                 // [2, E] int32 or int64
    const float* W  = (const float*)d_in[2];   // [64,128]
    const float* b  = (const float*)d_in[3];   // [64]
    float* out = (float*)d_out;

    const int E = in_sizes[1] / 2;             // 1,600,000

    sgc_mono<<<GRID, TPB>>>(x, ei, E, W, b, out);
}

// round 14
// speedup vs baseline: 1.8804x; 1.1049x over previous
#include <cuda_runtime.h>
#include <cuda_fp16.h>
#include <cstdint>

#define N_NODES 100000
#define FEAT    64
#define NF      (N_NODES * FEAT)
#define E_MAX   1700000
#define GRID    296            // 2 blocks/SM on 148 SMs (co-resident, barrier-safe)
#define TPB     512
#define CHUNK   338            // ceil(N_NODES / GRID)
#define NBAR    7
#define NTILES  (N_NODES / 16) // 6250 row-tiles of 16

// Scratch: device globals (no allocations allowed). Zero-initialized.
// g_cnt invariant: zero at entry to every launch (re-zeroed in phase 4).
__device__ __align__(16) __half2 g_uh[NF / 2];   // fp16 feature buffers
__device__ __align__(16) __half2 g_uh2[NF / 2];
__device__ int   g_cnt[N_NODES];
__device__ int   g_off[N_NODES + 1];
__device__ int   g_cur[N_NODES];
__device__ int   g_adj[E_MAX];
__device__ int   g_blk[GRID];
__device__ float g_dinv[N_NODES];    // (deg)^{-1/2}, deg includes self-loop
__device__ float g_dinv2[N_NODES];   // (deg)^{-1}
// Grid barrier state; slot k's flag resets at release of slot k+1 (circular
// over NBAR used slots), so state self-cleans every launch (replay-safe).
__device__ unsigned      g_bar_cnt[NBAR];
__device__ volatile int  g_bar_flag[NBAR];

// ---------------------------------------------------------------------------
__device__ __forceinline__ void grid_barrier(int slot) {
    __syncthreads();
    if (threadIdx.x == 0) {
        __threadfence();
        unsigned old = atomicAdd(&g_bar_cnt[slot], 1u);
        if (old == GRID - 1) {
            g_bar_cnt[slot] = 0;
            g_bar_flag[(slot + NBAR - 1) % NBAR] = 0;
            __threadfence();
            g_bar_flag[slot] = 1;
        } else {
            while (g_bar_flag[slot] == 0) { __nanosleep(64); }
            __threadfence();
        }
    }
    __syncthreads();
}

__device__ __forceinline__ int edge_idx(const void* ei, int E, int half, int e,
                                        int is64) {
    if (is64) return (int)((const long long*)ei)[(size_t)half * E + e];
    return ((const int*)ei)[(size_t)half * E + e];
}

__device__ __forceinline__ unsigned f2h2(float a, float b) {
    __half2 h = __floats2half2_rn(a, b);
    return *reinterpret_cast<unsigned*>(&h);
}
__device__ __forceinline__ float2 h2f2(unsigned u) {
    __half2 h = *reinterpret_cast<__half2*>(&u);
    return __half22float2(h);
}
__device__ __forceinline__ __half2 u2h(unsigned u) {
    return *reinterpret_cast<__half2*>(&u);
}

// ---------------------------------------------------------------------------
// Gather hop: ONE WARP per node, two 16-lane halves own contiguous halves of
// the edge list. Lane hl of each half owns features [4hl..4hl+3] (uint2 = 4
// fp16). 4 edges per half per iteration (4 independent gathers in flight),
// fp16 pairwise pre-sum (__hadd2) then fp32 accumulation. shfl_xor(16)
// combines the halves at the end.
template <int PASS>
__device__ void hop_phase(float* __restrict__ outp, const float* __restrict__ b) {
    const uint2* uin = reinterpret_cast<const uint2*>((PASS == 1) ? g_uh2 : g_uh);
    uint2* uout = reinterpret_cast<uint2*>((PASS == 0) ? g_uh2 : g_uh);
    int lane = threadIdx.x & 31;
    int half = lane >> 4;
    int hl   = lane & 15;
    int w    = threadIdx.x >> 5;         // 0..15 warps per block

    for (int node = blockIdx.x * 16 + w; node < N_NODES; node += GRID * 16) {
        int d   = g_off[node];
        int n   = g_off[node + 1] - d;
        int n0  = (n + 1) >> 1;              // half 0's share
        int beg = d + (half ? n0 : 0);
        int cnt = half ? (n - n0) : n0;

        float4 s = make_float4(0.f, 0.f, 0.f, 0.f);
        if (half == 0) {                     // self-loop term counted once
            uint2 v = uin[(size_t)node * 16 + hl];
            float2 f0 = h2f2(v.x), f1 = h2f2(v.y);
            s.x = f0.x; s.y = f0.y; s.z = f1.x; s.w = f1.y;
        }

        int i = beg;
        int end4 = beg + (cnt & ~3);
        for (; i < end4; i += 4) {           // 4 edges per half per iter
            int j0 = __ldg(&g_adj[i + 0]);
            int j1 = __ldg(&g_adj[i + 1]);
            int j2 = __ldg(&g_adj[i + 2]);
            int j3 = __ldg(&g_adj[i + 3]);
            uint2 v0 = __ldg(&uin[(size_t)j0 * 16 + hl]);
            uint2 v1 = __ldg(&uin[(size_t)j1 * 16 + hl]);
            uint2 v2 = __ldg(&uin[(size_t)j2 * 16 + hl]);
            uint2 v3 = __ldg(&uin[(size_t)j3 * 16 + hl]);
            __half2 p0 = __hadd2(u2h(v0.x), u2h(v1.x));   // fp16 pairwise
            __half2 p1 = __hadd2(u2h(v0.y), u2h(v1.y));
            __half2 q0 = __hadd2(u2h(v2.x), u2h(v3.x));
            __half2 q1 = __hadd2(u2h(v2.y), u2h(v3.y));
            float2 f0 = __half22float2(p0);
            float2 f1 = __half22float2(p1);
            float2 g0 = __half22float2(q0);
            float2 g1 = __half22float2(q1);
            s.x += f0.x + g0.x;  s.y += f0.y + g0.y;
            s.z += f1.x + g1.x;  s.w += f1.y + g1.y;
        }
        int endc = beg + cnt;
        for (; i < endc; i++) {              // 0..3 leftovers (exact fp32 add)
            int j = __ldg(&g_adj[i]);
            uint2 v = __ldg(&uin[(size_t)j * 16 + hl]);
            float2 f0 = h2f2(v.x), f1 = h2f2(v.y);
            s.x += f0.x; s.y += f0.y; s.z += f1.x; s.w += f1.y;
        }

        // combine halves
        s.x += __shfl_xor_sync(0xFFFFFFFFu, s.x, 16);
        s.y += __shfl_xor_sync(0xFFFFFFFFu, s.y, 16);
        s.z += __shfl_xor_sync(0xFFFFFFFFu, s.z, 16);
        s.w += __shfl_xor_sync(0xFFFFFFFFu, s.w, 16);

        if (half == 0) {
            if (PASS == 2) {
                float sc = g_dinv[node];
                float4 bb = __ldg(&reinterpret_cast<const float4*>(b)[hl]);
                float4 o;
                o.x = sc * s.x + bb.x;
                o.y = sc * s.y + bb.y;
                o.z = sc * s.z + bb.z;
                o.w = sc * s.w + bb.w;
                reinterpret_cast<float4*>(outp)[(size_t)node * 16 + hl] = o;
            } else {
                float sc = g_dinv2[node];
                uint2 o;
                o.x = f2h2(sc * s.x, sc * s.y);
                o.y = f2h2(sc * s.z, sc * s.w);
                uout[(size_t)node * 16 + hl] = o;
            }
        }
    }
}

// ---------------------------------------------------------------------------
__global__ void __launch_bounds__(TPB, 2)
sgc_mono(const float* __restrict__ x, const void* __restrict__ ei, int E,
         const float* __restrict__ W, const float* __restrict__ b,
         float* __restrict__ out) {
    __shared__ __align__(16) char s_mem[17472];   // Wh2 (GEMM) / bs (scan)
    int* bs = reinterpret_cast<int*>(s_mem);      // scan scratch (2048B)

    const int tid = threadIdx.x;
    const int bid = blockIdx.x;
    const int gthread = bid * TPB + tid;
    const int gstride = GRID * TPB;

    // ---- Block-local dtype detect (no grid dependency) ---------------------
    int any = 0;
    {
        const int* ei32 = (const int*)ei;
        for (int i = tid; i < 1024; i += TPB)
            any |= (ei32[2 * i + 1] != 0);
    }
    const int is64 = (__syncthreads_or(any) == 0);

    // ---- Phase 1: degree histogram (g_cnt is zero at entry) ----------------
    for (int e = gthread; e < E; e += gstride) {
        unsigned t = (unsigned)edge_idx(ei, E, 1, e, is64);
        if (t < N_NODES) atomicAdd(&g_cnt[t], 1);
    }
    grid_barrier(0);

    // ---- Phase 2: per-block chunk sums ------------------------------------
    {
        int beg = bid * CHUNK;
        int len = N_NODES - beg; if (len > CHUNK) len = CHUNK; if (len < 0) len = 0;
        int v = (tid < len) ? g_cnt[beg + tid] : 0;
        bs[tid] = v;
        __syncthreads();
        for (int off = TPB / 2; off > 0; off >>= 1) {
            if (tid < off) bs[tid] += bs[tid + off];
            __syncthreads();
        }
        if (tid == 0) g_blk[bid] = bs[0];
    }
    grid_barrier(1);

    // ---- Phase 3: block 0 scans the 296 block sums ------------------------
    if (bid == 0) {
        int v = (tid < GRID) ? g_blk[tid] : 0;
        bs[tid] = v;
        __syncthreads();
        for (int off = 1; off < TPB; off <<= 1) {    // Hillis-Steele inclusive
            int p = (tid >= off) ? bs[tid - off] : 0;
            __syncthreads();
            bs[tid] += p;
            __syncthreads();
        }
        if (tid < GRID) g_blk[tid] = bs[tid] - v;    // exclusive
        if (tid == 0) g_off[N_NODES] = bs[TPB - 1];
    }
    grid_barrier(2);

    // ---- Phase 4: per-chunk exclusive scan + dinv/dinv2 + g_cnt re-zero ----
    {
        int beg = bid * CHUNK;
        int len = N_NODES - beg; if (len > CHUNK) len = CHUNK; if (len < 0) len = 0;
        int c = (tid < len) ? g_cnt[beg + tid] : 0;
        bs[tid] = c;
        __syncthreads();
        for (int off = 1; off < TPB; off <<= 1) {
            int p = (tid >= off) ? bs[tid - off] : 0;
            __syncthreads();
            bs[tid] += p;
            __syncthreads();
        }
        if (tid < len) {
            int excl = g_blk[bid] + bs[tid] - c;
            int i = beg + tid;
            g_off[i] = excl;
            g_cur[i] = excl;
            g_cnt[i] = 0;                      // restore zero invariant
            float deg = (float)c + 1.0f;
            g_dinv[i]  = rsqrtf(deg);
            g_dinv2[i] = 1.0f / deg;
        }
    }
    grid_barrier(3);

    // ---- Phase 5: scatter (CSR fill) then tensor-core GEMM ------------------
    for (int e = gthread; e < E; e += gstride) {
        unsigned t = (unsigned)edge_idx(ei, E, 1, e, is64);
        unsigned s = (unsigned)edge_idx(ei, E, 0, e, is64);
        if (t >= N_NODES || s >= N_NODES) continue;
        int pos = atomicAdd(&g_cur[t], 1);
        if (pos < E_MAX) g_adj[pos] = (int)s;
    }
    // GEMM: u0[i,:] = dinv[i] * (x[i,:] @ W^T), stored fp16.
    // HMMA m16n8k16: warp computes a 16x64 tile, fp32 accumulate.
    {
        __syncthreads();   // bs scratch -> Wh2 reuse
        __half2* Wh2 = reinterpret_cast<__half2*>(s_mem);   // [n][kp], stride 68
        for (int i = tid; i < 64 * 64; i += TPB) {          // 4096 W half2-pairs
            int n = i >> 6, kp = i & 63;
            float2 wv = __ldg(&reinterpret_cast<const float2*>(W)[(size_t)n * 64 + kp]);
            Wh2[n * 68 + kp] = __floats2half2_rn(wv.x, wv.y);
        }
        __syncthreads();

        const float2* x2 = reinterpret_cast<const float2*>(x);
        int lane = tid & 31;
        int wrp  = tid >> 5;
        int qp = lane >> 2;     // lane/4
        int rp = lane & 3;      // lane%4

        for (int tile = bid * 16 + wrp; tile < NTILES; tile += GRID * 16) {
            int r0 = tile * 16 + qp;     // this thread's rows: r0 and r0+8

            float acc[8][4];
            #pragma unroll
            for (int nt = 0; nt < 8; nt++)
                acc[nt][0] = acc[nt][1] = acc[nt][2] = acc[nt][3] = 0.f;

            #pragma unroll
            for (int ks = 0; ks < 8; ks++) {
                int kb = ks * 8 + rp;
                float2 va0 = __ldg(&x2[(size_t)r0 * 64 + kb]);
                float2 va1 = __ldg(&x2[(size_t)(r0 + 8) * 64 + kb]);
                float2 va2 = __ldg(&x2[(size_t)r0 * 64 + kb + 4]);
                float2 va3 = __ldg(&x2[(size_t)(r0 + 8) * 64 + kb + 4]);
                unsigned a0 = f2h2(va0.x, va0.y);
                unsigned a1 = f2h2(va1.x, va1.y);
                unsigned a2 = f2h2(va2.x, va2.y);
                unsigned a3 = f2h2(va3.x, va3.y);

                #pragma unroll
                for (int nt = 0; nt < 8; nt++) {
                    int col = nt * 8 + qp;
                    __half2 b0h = Wh2[col * 68 + ks * 8 + rp];
                    __half2 b1h = Wh2[col * 68 + ks * 8 + rp + 4];
                    unsigned b0 = *reinterpret_cast<unsigned*>(&b0h);
                    unsigned b1 = *reinterpret_cast<unsigned*>(&b1h);
                    asm volatile(
                        "mma.sync.aligned.m16n8k16.row.col.f32.f16.f16.f32 "
                        "{%0,%1,%2,%3}, {%4,%5,%6,%7}, {%8,%9}, {%0,%1,%2,%3};"
                        : "+f"(acc[nt][0]), "+f"(acc[nt][1]),
                          "+f"(acc[nt][2]), "+f"(acc[nt][3])
                        : "r"(a0), "r"(a1), "r"(a2), "r"(a3), "r"(b0), "r"(b1));
                }
            }

            float sc0 = g_dinv[r0];
            float sc1 = g_dinv[r0 + 8];
            #pragma unroll
            for (int nt = 0; nt < 8; nt++) {
                g_uh[(size_t)r0 * 32 + nt * 4 + rp] =
                    __floats2half2_rn(sc0 * acc[nt][0], sc0 * acc[nt][1]);
                g_uh[(size_t)(r0 + 8) * 32 + nt * 4 + rp] =
                    __floats2half2_rn(sc1 * acc[nt][2], sc1 * acc[nt][3]);
            }
        }
    }
    grid_barrier(4);

    // ---- Phases 6-8: three gather hops -------------------------------------
    hop_phase<0>(nullptr, b);
    grid_barrier(5);
    hop_phase<1>(nullptr, b);
    grid_barrier(6);
    hop_phase<2>(out, b);
}

// ---------------------------------------------------------------------------
extern "C" void kernel_launch(void* const* d_in, const int* in_sizes, int n_in,
                              void* d_out, int out_size) {
    const float* x  = (const float*)d_in[0];   // [100000,128]
    const void*  ei = d_in[1];                 // [2, E] int32 or int64
    const float* W  = (const float*)d_in[2];   // [64,128]
    const float* b  = (const float*)d_in[3];   // [64]
    float* out = (float*)d_out;

    const int E = in_sizes[1] / 2;             // 1,600,000

    sgc_mono<<<GRID, TPB>>>(x, ei, E, W, b, out);
}

// round 15
// speedup vs baseline: 2.1436x; 1.1400x over previous
#include <cuda_runtime.h>
#include <cuda_fp16.h>
#include <cstdint>

#define N_NODES 100000
#define FEAT    64
#define NF      (N_NODES * FEAT)
#define E_MAX   1700000
#define GRID    296            // 2 blocks/SM on 148 SMs (co-resident, barrier-safe)
#define TPB     512
#define CHUNK   338            // ceil(N_NODES / GRID)
#define NBAR    4
#define NTILES  (N_NODES / 16) // 6250 row-tiles of 16

// Scratch: device globals (no allocations allowed). Zero-initialized.
// g_cnt invariant: zero at entry to every launch (re-zeroed in phase 4).
__device__ __align__(16) __half2 g_uh[NF / 2];   // fp16 feature buffers
__device__ __align__(16) __half2 g_uh2[NF / 2];
__device__ int   g_cnt[N_NODES];
__device__ int   g_off[N_NODES + 1];
__device__ int   g_cur[N_NODES];
__device__ int   g_adj[E_MAX];
__device__ int   g_blk[GRID];
__device__ float g_dinv[N_NODES];    // (deg)^{-1/2}, deg includes self-loop
__device__ float g_dinv2[N_NODES];   // (deg)^{-1}
// Grid barrier state; slot k's flag resets at release of slot k+1 (circular
// over NBAR used slots), so state self-cleans every launch (replay-safe).
__device__ unsigned      g_bar_cnt[NBAR];
__device__ volatile int  g_bar_flag[NBAR];

// ---------------------------------------------------------------------------
__device__ __forceinline__ void grid_barrier(int slot) {
    __syncthreads();
    if (threadIdx.x == 0) {
        __threadfence();
        unsigned old = atomicAdd(&g_bar_cnt[slot], 1u);
        if (old == GRID - 1) {
            g_bar_cnt[slot] = 0;
            g_bar_flag[(slot + NBAR - 1) % NBAR] = 0;
            __threadfence();
            g_bar_flag[slot] = 1;
        } else {
            while (g_bar_flag[slot] == 0) { __nanosleep(64); }
            __threadfence();
        }
    }
    __syncthreads();
}

__device__ __forceinline__ int edge_idx(const void* ei, int E, int half, int e,
                                        int is64) {
    if (is64) return (int)((const long long*)ei)[(size_t)half * E + e];
    return ((const int*)ei)[(size_t)half * E + e];
}

__device__ __forceinline__ unsigned f2h2(float a, float b) {
    __half2 h = __floats2half2_rn(a, b);
    return *reinterpret_cast<unsigned*>(&h);
}
__device__ __forceinline__ float2 h2f2(unsigned u) {
    __half2 h = *reinterpret_cast<__half2*>(&u);
    return __half22float2(h);
}
__device__ __forceinline__ __half2 u2h(unsigned u) {
    return *reinterpret_cast<__half2*>(&u);
}

// ---------------------------------------------------------------------------
// Kernel 1: CSR build (hist, scan, scatter) + folded tensor-core GEMM.
__global__ void __launch_bounds__(TPB, 2)
sgc_build(const float* __restrict__ x, const void* __restrict__ ei, int E,
          const float* __restrict__ W) {
    __shared__ __align__(16) char s_mem[17472];   // Wh2 (GEMM) / bs (scan)
    int* bs = reinterpret_cast<int*>(s_mem);      // scan scratch (2048B)

    const int tid = threadIdx.x;
    const int bid = blockIdx.x;
    const int gthread = bid * TPB + tid;
    const int gstride = GRID * TPB;

    // ---- Block-local dtype detect (no grid dependency) ---------------------
    int any = 0;
    {
        const int* ei32 = (const int*)ei;
        for (int i = tid; i < 1024; i += TPB)
            any |= (ei32[2 * i + 1] != 0);
    }
    const int is64 = (__syncthreads_or(any) == 0);

    // ---- Phase 1: degree histogram (g_cnt is zero at entry) ----------------
    for (int e = gthread; e < E; e += gstride) {
        unsigned t = (unsigned)edge_idx(ei, E, 1, e, is64);
        if (t < N_NODES) atomicAdd(&g_cnt[t], 1);
    }
    grid_barrier(0);

    // ---- Phase 2: per-block chunk sums ------------------------------------
    {
        int beg = bid * CHUNK;
        int len = N_NODES - beg; if (len > CHUNK) len = CHUNK; if (len < 0) len = 0;
        int v = (tid < len) ? g_cnt[beg + tid] : 0;
        bs[tid] = v;
        __syncthreads();
        for (int off = TPB / 2; off > 0; off >>= 1) {
            if (tid < off) bs[tid] += bs[tid + off];
            __syncthreads();
        }
        if (tid == 0) g_blk[bid] = bs[0];
    }
    grid_barrier(1);

    // ---- Phase 3: block 0 scans the 296 block sums ------------------------
    if (bid == 0) {
        int v = (tid < GRID) ? g_blk[tid] : 0;
        bs[tid] = v;
        __syncthreads();
        for (int off = 1; off < TPB; off <<= 1) {    // Hillis-Steele inclusive
            int p = (tid >= off) ? bs[tid - off] : 0;
            __syncthreads();
            bs[tid] += p;
            __syncthreads();
        }
        if (tid < GRID) g_blk[tid] = bs[tid] - v;    // exclusive
        if (tid == 0) g_off[N_NODES] = bs[TPB - 1];
    }
    grid_barrier(2);

    // ---- Phase 4: per-chunk exclusive scan + dinv/dinv2 + g_cnt re-zero ----
    {
        int beg = bid * CHUNK;
        int len = N_NODES - beg; if (len > CHUNK) len = CHUNK; if (len < 0) len = 0;
        int c = (tid < len) ? g_cnt[beg + tid] : 0;
        bs[tid] = c;
        __syncthreads();
        for (int off = 1; off < TPB; off <<= 1) {
            int p = (tid >= off) ? bs[tid - off] : 0;
            __syncthreads();
            bs[tid] += p;
            __syncthreads();
        }
        if (tid < len) {
            int excl = g_blk[bid] + bs[tid] - c;
            int i = beg + tid;
            g_off[i] = excl;
            g_cur[i] = excl;
            g_cnt[i] = 0;                      // restore zero invariant
            float deg = (float)c + 1.0f;
            g_dinv[i]  = rsqrtf(deg);
            g_dinv2[i] = 1.0f / deg;
        }
    }
    grid_barrier(3);

    // ---- Phase 5: scatter (CSR fill) then tensor-core GEMM ------------------
    for (int e = gthread; e < E; e += gstride) {
        unsigned t = (unsigned)edge_idx(ei, E, 1, e, is64);
        unsigned s = (unsigned)edge_idx(ei, E, 0, e, is64);
        if (t >= N_NODES || s >= N_NODES) continue;
        int pos = atomicAdd(&g_cur[t], 1);
        if (pos < E_MAX) g_adj[pos] = (int)s;
    }
    // GEMM: u0[i,:] = dinv[i] * (x[i,:] @ W^T), stored fp16.
    // HMMA m16n8k16: warp computes a 16x64 tile, fp32 accumulate.
    {
        __syncthreads();   // bs scratch -> Wh2 reuse
        __half2* Wh2 = reinterpret_cast<__half2*>(s_mem);   // [n][kp], stride 68
        for (int i = tid; i < 64 * 64; i += TPB) {          // 4096 W half2-pairs
            int n = i >> 6, kp = i & 63;
            float2 wv = __ldg(&reinterpret_cast<const float2*>(W)[(size_t)n * 64 + kp]);
            Wh2[n * 68 + kp] = __floats2half2_rn(wv.x, wv.y);
        }
        __syncthreads();

        const float2* x2 = reinterpret_cast<const float2*>(x);
        int lane = tid & 31;
        int wrp  = tid >> 5;
        int qp = lane >> 2;     // lane/4
        int rp = lane & 3;      // lane%4

        for (int tile = bid * 16 + wrp; tile < NTILES; tile += GRID * 16) {
            int r0 = tile * 16 + qp;     // this thread's rows: r0 and r0+8

            float acc[8][4];
            #pragma unroll
            for (int nt = 0; nt < 8; nt++)
                acc[nt][0] = acc[nt][1] = acc[nt][2] = acc[nt][3] = 0.f;

            #pragma unroll
            for (int ks = 0; ks < 8; ks++) {
                int kb = ks * 8 + rp;
                float2 va0 = __ldg(&x2[(size_t)r0 * 64 + kb]);
                float2 va1 = __ldg(&x2[(size_t)(r0 + 8) * 64 + kb]);
                float2 va2 = __ldg(&x2[(size_t)r0 * 64 + kb + 4]);
                float2 va3 = __ldg(&x2[(size_t)(r0 + 8) * 64 + kb + 4]);
                unsigned a0 = f2h2(va0.x, va0.y);
                unsigned a1 = f2h2(va1.x, va1.y);
                unsigned a2 = f2h2(va2.x, va2.y);
                unsigned a3 = f2h2(va3.x, va3.y);

                #pragma unroll
                for (int nt = 0; nt < 8; nt++) {
                    int col = nt * 8 + qp;
                    __half2 b0h = Wh2[col * 68 + ks * 8 + rp];
                    __half2 b1h = Wh2[col * 68 + ks * 8 + rp + 4];
                    unsigned b0 = *reinterpret_cast<unsigned*>(&b0h);
                    unsigned b1 = *reinterpret_cast<unsigned*>(&b1h);
                    asm volatile(
                        "mma.sync.aligned.m16n8k16.row.col.f32.f16.f16.f32 "
                        "{%0,%1,%2,%3}, {%4,%5,%6,%7}, {%8,%9}, {%0,%1,%2,%3};"
                        : "+f"(acc[nt][0]), "+f"(acc[nt][1]),
                          "+f"(acc[nt][2]), "+f"(acc[nt][3])
                        : "r"(a0), "r"(a1), "r"(a2), "r"(a3), "r"(b0), "r"(b1));
                }
            }

            float sc0 = g_dinv[r0];
            float sc1 = g_dinv[r0 + 8];
            #pragma unroll
            for (int nt = 0; nt < 8; nt++) {
                g_uh[(size_t)r0 * 32 + nt * 4 + rp] =
                    __floats2half2_rn(sc0 * acc[nt][0], sc0 * acc[nt][1]);
                g_uh[(size_t)(r0 + 8) * 32 + nt * 4 + rp] =
                    __floats2half2_rn(sc1 * acc[nt][2], sc1 * acc[nt][3]);
            }
        }
    }
}

// ---------------------------------------------------------------------------
// Kernels 2-4: gather hop. ONE WARP per node, two 16-lane halves own
// contiguous halves of the edge list. Lane hl owns features [4hl..4hl+3]
// (uint2 = 4 fp16). 4 edges per half per iteration, fp16 pairwise pre-sum
// then fp32 accumulation; shfl_xor(16) combines halves. Lightweight kernel
// (low regs) -> high occupancy -> deep gather window.
template <int PASS>
__global__ void __launch_bounds__(256)
sgc_hop(float* __restrict__ outp, const float* __restrict__ b) {
    const uint2* uin = reinterpret_cast<const uint2*>((PASS == 1) ? g_uh2 : g_uh);
    uint2* uout = reinterpret_cast<uint2*>((PASS == 0) ? g_uh2 : g_uh);
    int lane = threadIdx.x & 31;
    int half = lane >> 4;
    int hl   = lane & 15;

    int node = blockIdx.x * 8 + (threadIdx.x >> 5);
    if (node >= N_NODES) return;

    int d   = g_off[node];
    int n   = g_off[node + 1] - d;
    int n0  = (n + 1) >> 1;              // half 0's share
    int beg = d + (half ? n0 : 0);
    int cnt = half ? (n - n0) : n0;

    float4 s = make_float4(0.f, 0.f, 0.f, 0.f);
    if (half == 0) {                     // self-loop term counted once
        uint2 v = uin[(size_t)node * 16 + hl];
        float2 f0 = h2f2(v.x), f1 = h2f2(v.y);
        s.x = f0.x; s.y = f0.y; s.z = f1.x; s.w = f1.y;
    }

    int i = beg;
    int end4 = beg + (cnt & ~3);
    for (; i < end4; i += 4) {           // 4 edges per half per iter
        int j0 = __ldg(&g_adj[i + 0]);
        int j1 = __ldg(&g_adj[i + 1]);
        int j2 = __ldg(&g_adj[i + 2]);
        int j3 = __ldg(&g_adj[i + 3]);
        uint2 v0 = __ldg(&uin[(size_t)j0 * 16 + hl]);
        uint2 v1 = __ldg(&uin[(size_t)j1 * 16 + hl]);
        uint2 v2 = __ldg(&uin[(size_t)j2 * 16 + hl]);
        uint2 v3 = __ldg(&uin[(size_t)j3 * 16 + hl]);
        __half2 p0 = __hadd2(u2h(v0.x), u2h(v1.x));   // fp16 pairwise
        __half2 p1 = __hadd2(u2h(v0.y), u2h(v1.y));
        __half2 q0 = __hadd2(u2h(v2.x), u2h(v3.x));
        __half2 q1 = __hadd2(u2h(v2.y), u2h(v3.y));
        float2 f0 = __half22float2(p0);
        float2 f1 = __half22float2(p1);
        float2 g0 = __half22float2(q0);
        float2 g1 = __half22float2(q1);
        s.x += f0.x + g0.x;  s.y += f0.y + g0.y;
        s.z += f1.x + g1.x;  s.w += f1.y + g1.y;
    }
    int endc = beg + cnt;
    for (; i < endc; i++) {              // 0..3 leftovers (exact fp32 add)
        int j = __ldg(&g_adj[i]);
        uint2 v = __ldg(&uin[(size_t)j * 16 + hl]);
        float2 f0 = h2f2(v.x), f1 = h2f2(v.y);
        s.x += f0.x; s.y += f0.y; s.z += f1.x; s.w += f1.y;
    }

    // combine halves
    s.x += __shfl_xor_sync(0xFFFFFFFFu, s.x, 16);
    s.y += __shfl_xor_sync(0xFFFFFFFFu, s.y, 16);
    s.z += __shfl_xor_sync(0xFFFFFFFFu, s.z, 16);
    s.w += __shfl_xor_sync(0xFFFFFFFFu, s.w, 16);

    if (half == 0) {
        if (PASS == 2) {
            float sc = g_dinv[node];
            float4 bb = __ldg(&reinterpret_cast<const float4*>(b)[hl]);
            float4 o;
            o.x = sc * s.x + bb.x;
            o.y = sc * s.y + bb.y;
            o.z = sc * s.z + bb.z;
            o.w = sc * s.w + bb.w;
            reinterpret_cast<float4*>(outp)[(size_t)node * 16 + hl] = o;
        } else {
            float sc = g_dinv2[node];
            uint2 o;
            o.x = f2h2(sc * s.x, sc * s.y);
            o.y = f2h2(sc * s.z, sc * s.w);
            uout[(size_t)node * 16 + hl] = o;
        }
    }
}

// ---------------------------------------------------------------------------
extern "C" void kernel_launch(void* const* d_in, const int* in_sizes, int n_in,
                              void* d_out, int out_size) {
    const float* x  = (const float*)d_in[0];   // [100000,128]
    const void*  ei = d_in[1];                 // [2, E] int32 or int64
    const float* W  = (const float*)d_in[2];   // [64,128]
    const float* b  = (const float*)d_in[3];   // [64]
    float* out = (float*)d_out;

    const int E = in_sizes[1] / 2;             // 1,600,000

    sgc_build<<<GRID, TPB>>>(x, ei, E, W);

    const int hb = (N_NODES + 7) / 8;          // warp-per-node, 8 warps/block
    sgc_hop<0><<<hb, 256>>>(nullptr, b);
    sgc_hop<1><<<hb, 256>>>(nullptr, b);
    sgc_hop<2><<<hb, 256>>>(out, b);
}